// round 5
// baseline (speedup 1.0000x reference)
#include <cuda_runtime.h>
#include <math_constants.h>

// MeanMaxPooling: N=4, E=64, L=512, D=256
// in[0]: doc_state    (N, L, D) float32
// in[1]: nodes_mapping(N, E, L) float32 (0/1)
// in[2]: nodes_len    (N, E)    float32  (unused: == popcount of mask row)
// out  : (N, E, 2*D)  float32  [0:D]=max over masked states (incl. 0), [D:2D]=mean
//
// Warp-autonomous: one warp per (ne, d-half). No shared memory, no barriers.

#define N_ 4
#define E_ 64
#define L_ 512
#define D_ 256
#define FULL_MASK 0xffffffffu

__global__ __launch_bounds__(64)
void meanmax_kernel(const float* __restrict__ doc_state,
                    const float* __restrict__ nodes_mapping,
                    float* __restrict__ out)
{
    const int ne   = blockIdx.x;          // (n, e) pair, 0..255
    const int n    = ne >> 6;             // ne / E
    const int half = threadIdx.x >> 5;    // warp 0 -> d[0:128), warp 1 -> d[128:256)
    const int lane = threadIdx.x & 31;

    // --- one round trip: whole 512-float mask row, 4 coalesced float4 loads ---
    // lane holds tokens {128g + 4*lane + c : c=0..3, g=0..3}
    const float4* mrow4 = (const float4*)(nodes_mapping + (size_t)ne * L_);
    float4 mv[4];
    #pragma unroll
    for (int g = 0; g < 4; ++g) mv[g] = mrow4[g * 32 + lane];

    // this lane's float4 d-slot within each token row
    const float4* doc4 = (const float4*)(doc_state + (size_t)n * L_ * D_)
                         + half * 32 + lane;

    float4 sum = make_float4(0.f, 0.f, 0.f, 0.f);
    float4 mx  = make_float4(-CUDART_INF_F, -CUDART_INF_F,
                             -CUDART_INF_F, -CUDART_INF_F);
    int tot = 0;

    #pragma unroll
    for (int g = 0; g < 4; ++g) {
        // 4 independent bit-chains; chain c, bit l  ->  token 128g + 4l + c
        unsigned b0 = __ballot_sync(FULL_MASK, mv[g].x != 0.0f);
        unsigned b1 = __ballot_sync(FULL_MASK, mv[g].y != 0.0f);
        unsigned b2 = __ballot_sync(FULL_MASK, mv[g].z != 0.0f);
        unsigned b3 = __ballot_sync(FULL_MASK, mv[g].w != 0.0f);
        tot += __popc(b0) + __popc(b1) + __popc(b2) + __popc(b3);

        const int tb = g * 128;
        while (b0 | b1 | b2 | b3) {
            const bool o0 = (b0 != 0u), o1 = (b1 != 0u),
                       o2 = (b2 != 0u), o3 = (b3 != 0u);
            const int t0 = tb + 4 * (__ffs(b0) - 1) + 0;
            const int t1 = tb + 4 * (__ffs(b1) - 1) + 1;
            const int t2 = tb + 4 * (__ffs(b2) - 1) + 2;
            const int t3 = tb + 4 * (__ffs(b3) - 1) + 3;
            b0 &= b0 - 1u; b1 &= b1 - 1u; b2 &= b2 - 1u; b3 &= b3 - 1u;

            float4 v0, v1, v2, v3;
            if (o0) v0 = doc4[(size_t)t0 * (D_ / 4)];
            if (o1) v1 = doc4[(size_t)t1 * (D_ / 4)];
            if (o2) v2 = doc4[(size_t)t2 * (D_ / 4)];
            if (o3) v3 = doc4[(size_t)t3 * (D_ / 4)];

            if (o0) {
                sum.x += v0.x; sum.y += v0.y; sum.z += v0.z; sum.w += v0.w;
                mx.x = fmaxf(mx.x, v0.x); mx.y = fmaxf(mx.y, v0.y);
                mx.z = fmaxf(mx.z, v0.z); mx.w = fmaxf(mx.w, v0.w);
            }
            if (o1) {
                sum.x += v1.x; sum.y += v1.y; sum.z += v1.z; sum.w += v1.w;
                mx.x = fmaxf(mx.x, v1.x); mx.y = fmaxf(mx.y, v1.y);
                mx.z = fmaxf(mx.z, v1.z); mx.w = fmaxf(mx.w, v1.w);
            }
            if (o2) {
                sum.x += v2.x; sum.y += v2.y; sum.z += v2.z; sum.w += v2.w;
                mx.x = fmaxf(mx.x, v2.x); mx.y = fmaxf(mx.y, v2.y);
                mx.z = fmaxf(mx.z, v2.z); mx.w = fmaxf(mx.w, v2.w);
            }
            if (o3) {
                sum.x += v3.x; sum.y += v3.y; sum.z += v3.z; sum.w += v3.w;
                mx.x = fmaxf(mx.x, v3.x); mx.y = fmaxf(mx.y, v3.y);
                mx.z = fmaxf(mx.z, v3.z); mx.w = fmaxf(mx.w, v3.w);
            }
        }
    }

    // mask-broadcast semantics: any unselected token contributes 0 to the max
    if (tot < L_) {
        mx.x = fmaxf(mx.x, 0.f); mx.y = fmaxf(mx.y, 0.f);
        mx.z = fmaxf(mx.z, 0.f); mx.w = fmaxf(mx.w, 0.f);
    }
    const float inv = 1.0f / (float)((tot > 0) ? tot : 1);
    sum.x *= inv; sum.y *= inv; sum.z *= inv; sum.w *= inv;

    // direct final stores: no inter-warp merge needed
    float4* orow4 = (float4*)(out + (size_t)ne * (2 * D_));
    orow4[half * 32 + lane]            = mx;   // max   half
    orow4[(D_ / 4) + half * 32 + lane] = sum;  // mean  half
}

extern "C" void kernel_launch(void* const* d_in, const int* in_sizes, int n_in,
                              void* d_out, int out_size)
{
    const float* doc_state     = (const float*)d_in[0];
    const float* nodes_mapping = (const float*)d_in[1];
    float* out = (float*)d_out;

    meanmax_kernel<<<N_ * E_, 64>>>(doc_state, nodes_mapping, out);
}

// round 6
// speedup vs baseline: 1.5685x; 1.5685x over previous
#include <cuda_runtime.h>
#include <math_constants.h>

// MeanMaxPooling: N=4, E=64, L=512, D=256
// in[0]: doc_state    (N, L, D) float32
// in[1]: nodes_mapping(N, E, L) float32 (0/1)
// in[2]: nodes_len    (N, E)    float32 (unused; == popcount of mask row)
// out  : (N, E, 2*D)  float32  [0:D]=max over masked states (incl. 0), [D:2D]=mean
//
// Warp-autonomous: warp = (ne, d-eighth). No atomics, no __syncthreads, no merge.

#define N_ 4
#define E_ 64
#define L_ 512
#define D_ 256
#define NW 8                 // warps per CTA = d-eighths; lane owns one d
#define FULL_MASK 0xffffffffu

__global__ __launch_bounds__(NW * 32)
void meanmax_kernel(const float* __restrict__ doc_state,
                    const float* __restrict__ nodes_mapping,
                    float* __restrict__ out)
{
    const int ne   = blockIdx.x;          // (n, e) pair, 0..255
    const int n    = ne >> 6;
    const int w    = threadIdx.x >> 5;    // d-eighth
    const int lane = threadIdx.x & 31;
    const int d    = w * 32 + lane;       // this thread's feature index

    __shared__ int s_idx[NW][L_];         // warp-private compact token lists (16 KB)

    // ---- full mask row: 4 coalesced float4 loads (lane -> tokens 128g+4*lane+c)
    const float4* mrow4 = (const float4*)(nodes_mapping + (size_t)ne * L_);
    float4 mv[4];
    #pragma unroll
    for (int g = 0; g < 4; ++g) mv[g] = mrow4[g * 32 + lane];

    // ---- warp-private compaction via ballot + prefix popc (no atomics)
    const unsigned below = (1u << lane) - 1u;
    int cnt = 0;
    #pragma unroll
    for (int g = 0; g < 4; ++g) {
        const float mc[4] = { mv[g].x, mv[g].y, mv[g].z, mv[g].w };
        #pragma unroll
        for (int c = 0; c < 4; ++c) {
            const unsigned b = __ballot_sync(FULL_MASK, mc[c] != 0.0f);
            if ((b >> lane) & 1u)
                s_idx[w][cnt + __popc(b & below)] = 128 * g + 4 * lane + c;
            cnt += __popc(b);
        }
    }
    __syncwarp();

    // ---- gather: batches of 8 independent loads, indices from smem (broadcast LDS)
    const float* doc = doc_state + (size_t)n * L_ * D_ + d;

    float smax = -CUDART_INF_F;
    float ssum = 0.0f;

    for (int i = 0; i < cnt; i += 8) {
        int  l[8];
        bool ok[8];
        #pragma unroll
        for (int j = 0; j < 8; ++j) {
            ok[j] = (i + j < cnt);
            l[j]  = s_idx[w][ok[j] ? (i + j) : i];
        }
        float v[8];
        #pragma unroll
        for (int j = 0; j < 8; ++j)
            if (ok[j]) v[j] = doc[(size_t)l[j] * D_];
        #pragma unroll
        for (int j = 0; j < 8; ++j) {
            if (ok[j]) {
                ssum += v[j];
                smax = fmaxf(smax, v[j]);
            }
        }
    }

    // mask-broadcast semantics: any unselected token contributes 0 to the max
    if (cnt < L_) smax = fmaxf(smax, 0.0f);
    const float inv = 1.0f / (float)((cnt > 0) ? cnt : 1);

    // ---- direct final stores (coalesced 128B per warp per half)
    float* orow = out + (size_t)ne * (2 * D_);
    orow[d]       = smax;
    orow[D_ + d]  = ssum * inv;
}

extern "C" void kernel_launch(void* const* d_in, const int* in_sizes, int n_in,
                              void* d_out, int out_size)
{
    const float* doc_state     = (const float*)d_in[0];
    const float* nodes_mapping = (const float*)d_in[1];
    float* out = (float*)d_out;

    meanmax_kernel<<<N_ * E_, NW * 32>>>(doc_state, nodes_mapping, out);
}

// round 7
// speedup vs baseline: 1.8889x; 1.2043x over previous
#include <cuda_runtime.h>
#include <math_constants.h>

// MeanMaxPooling: N=4, E=64, L=512, D=256
// in[0]: doc_state    (N, L, D) float32
// in[1]: nodes_mapping(N, E, L) float32 (0/1)
// in[2]: nodes_len    (N, E)    float32 (unused; == popcount of mask row)
// out  : (N, E, 2*D)  float32  [0:D]=max over masked states (incl. 0), [D:2D]=mean
//
// CTA per (n,e): 16 warps, warp w owns tokens [32w, 32w+32).
// Ballot compaction (no atomics), one barrier, fully parallel scalar merge.

#define N_ 4
#define E_ 64
#define L_ 512
#define D_ 256
#define NW 16
#define FULL_MASK 0xffffffffu

__global__ __launch_bounds__(NW * 32, 2)
void meanmax_kernel(const float* __restrict__ doc_state,
                    const float* __restrict__ nodes_mapping,
                    float* __restrict__ out)
{
    const int ne   = blockIdx.x;       // (n, e)
    const int n    = ne >> 6;
    const int tid  = threadIdx.x;
    const int w    = tid >> 5;         // 32-token chunk
    const int lane = tid & 31;

    __shared__ float s_max[NW][D_];    // 16 KB
    __shared__ float s_sum[NW][D_];    // 16 KB
    __shared__ int   s_cnt[NW];

    // warp reads its 32 mask values (one coalesced 128B line) -> bitmask
    const float mval = nodes_mapping[(size_t)ne * L_ + w * 32 + lane];
    unsigned mb = __ballot_sync(FULL_MASK, mval != 0.0f);
    if (lane == 0) s_cnt[w] = __popc(mb);

    const float4* doc4 = (const float4*)(doc_state + (size_t)n * L_ * D_);
    const int base = w * 32;

    float4 s0 = make_float4(0.f, 0.f, 0.f, 0.f), s1 = s0;
    float4 m0 = make_float4(-CUDART_INF_F, -CUDART_INF_F, -CUDART_INF_F, -CUDART_INF_F);
    float4 m1 = m0;

    // gather: ~3.2 tokens expected -> usually one batch of 4 (8 indep LDG.128)
    while (mb) {
        int  l[4];
        bool ok[4];
        #pragma unroll
        for (int j = 0; j < 4; ++j) {
            ok[j] = (mb != 0u);
            l[j]  = ok[j] ? (__ffs(mb) - 1) : 0;
            mb &= mb - 1u;
        }
        float4 a[4], b[4];
        #pragma unroll
        for (int j = 0; j < 4; ++j) {
            if (ok[j]) {
                const float4* p = doc4 + (size_t)(base + l[j]) * (D_ / 4);
                a[j] = p[lane];        // d = 4*lane..4*lane+3
                b[j] = p[32 + lane];   // d = 128+4*lane..
            }
        }
        #pragma unroll
        for (int j = 0; j < 4; ++j) {
            if (ok[j]) {
                s0.x += a[j].x; s0.y += a[j].y; s0.z += a[j].z; s0.w += a[j].w;
                s1.x += b[j].x; s1.y += b[j].y; s1.z += b[j].z; s1.w += b[j].w;
                m0.x = fmaxf(m0.x, a[j].x); m0.y = fmaxf(m0.y, a[j].y);
                m0.z = fmaxf(m0.z, a[j].z); m0.w = fmaxf(m0.w, a[j].w);
                m1.x = fmaxf(m1.x, b[j].x); m1.y = fmaxf(m1.y, b[j].y);
                m1.z = fmaxf(m1.z, b[j].z); m1.w = fmaxf(m1.w, b[j].w);
            }
        }
    }

    *(float4*)&s_sum[w][4 * lane]       = s0;
    *(float4*)&s_sum[w][128 + 4 * lane] = s1;
    *(float4*)&s_max[w][4 * lane]       = m0;
    *(float4*)&s_max[w][128 + 4 * lane] = m1;
    __syncthreads();

    // fully parallel merge: each of 512 threads owns ONE output scalar.
    // warps 0-7 -> max[d], warps 8-15 -> mean[d]  (uniform branch per warp)
    {
        const bool is_max = (tid < 256);
        const int  d = tid & 255;

        // total selected count (broadcast LDS reads, conflict-free)
        int tot = 0;
        #pragma unroll
        for (int q = 0; q < NW; ++q) tot += s_cnt[q];

        float r;
        if (is_max) {
            r = s_max[0][d];
            #pragma unroll
            for (int q = 1; q < NW; ++q) r = fmaxf(r, s_max[q][d]);
            if (tot < L_) r = fmaxf(r, 0.0f);   // masked-out tokens add 0 to max
            out[(size_t)ne * (2 * D_) + d] = r;
        } else {
            r = s_sum[0][d];
            #pragma unroll
            for (int q = 1; q < NW; ++q) r += s_sum[q][d];
            r *= 1.0f / (float)((tot > 0) ? tot : 1);
            out[(size_t)ne * (2 * D_) + D_ + d] = r;
        }
    }
}

extern "C" void kernel_launch(void* const* d_in, const int* in_sizes, int n_in,
                              void* d_out, int out_size)
{
    const float* doc_state     = (const float*)d_in[0];
    const float* nodes_mapping = (const float*)d_in[1];
    float* out = (float*)d_out;

    meanmax_kernel<<<N_ * E_, NW * 32>>>(doc_state, nodes_mapping, out);
}

// round 8
// speedup vs baseline: 2.0038x; 1.0608x over previous
#include <cuda_runtime.h>
#include <math_constants.h>

// MeanMaxPooling: N=4, E=64, L=512, D=256
// in[0]: doc_state    (N, L, D) float32
// in[1]: nodes_mapping(N, E, L) float32 (0/1)
// in[2]: nodes_len    (N, E)    float32  (== sum(mask); loaded early, fully overlapped)
// out  : (N, E, 2*D)  float32  [0:D]=max over masked states (incl. 0), [D:2D]=mean
//
// CTA per (n,e): 16 warps, warp w owns tokens [32w, 32w+32).
// Ballot compaction (no atomics), one barrier, fully parallel scalar merge.

#define N_ 4
#define E_ 64
#define L_ 512
#define D_ 256
#define NW 16
#define FULL_MASK 0xffffffffu

__global__ __launch_bounds__(NW * 32, 2)
void meanmax_kernel(const float* __restrict__ doc_state,
                    const float* __restrict__ nodes_mapping,
                    const float* __restrict__ nodes_len,
                    float* __restrict__ out)
{
    const int ne   = blockIdx.x;       // (n, e)
    const int n    = ne >> 6;
    const int tid  = threadIdx.x;
    const int w    = tid >> 5;         // 32-token chunk
    const int lane = tid & 31;

    __shared__ float s_max[NW][D_];    // 16 KB
    __shared__ float s_sum[NW][D_];    // 16 KB

    // issued first -> latency fully hidden behind mask RT + gather RT
    const float len = nodes_len[ne];

    // warp reads its 32 mask values (one coalesced 128B line) -> bitmask
    const float mval = nodes_mapping[(size_t)ne * L_ + w * 32 + lane];
    unsigned mb = __ballot_sync(FULL_MASK, mval != 0.0f);

    const float4* doc4 = (const float4*)(doc_state + (size_t)n * L_ * D_);
    const int base = w * 32;

    float4 s0 = make_float4(0.f, 0.f, 0.f, 0.f), s1 = s0;
    float4 m0 = make_float4(-CUDART_INF_F, -CUDART_INF_F, -CUDART_INF_F, -CUDART_INF_F);
    float4 m1 = m0;

    // gather: ~3.2 tokens expected -> usually one batch of 4 (8 indep LDG.128)
    while (mb) {
        int  l[4];
        bool ok[4];
        #pragma unroll
        for (int j = 0; j < 4; ++j) {
            ok[j] = (mb != 0u);
            l[j]  = ok[j] ? (__ffs(mb) - 1) : 0;
            mb &= mb - 1u;
        }
        float4 a[4], b[4];
        #pragma unroll
        for (int j = 0; j < 4; ++j) {
            if (ok[j]) {
                const float4* p = doc4 + (size_t)(base + l[j]) * (D_ / 4);
                a[j] = p[lane];        // d = 4*lane..4*lane+3
                b[j] = p[32 + lane];   // d = 128+4*lane..
            }
        }
        #pragma unroll
        for (int j = 0; j < 4; ++j) {
            if (ok[j]) {
                s0.x += a[j].x; s0.y += a[j].y; s0.z += a[j].z; s0.w += a[j].w;
                s1.x += b[j].x; s1.y += b[j].y; s1.z += b[j].z; s1.w += b[j].w;
                m0.x = fmaxf(m0.x, a[j].x); m0.y = fmaxf(m0.y, a[j].y);
                m0.z = fmaxf(m0.z, a[j].z); m0.w = fmaxf(m0.w, a[j].w);
                m1.x = fmaxf(m1.x, b[j].x); m1.y = fmaxf(m1.y, b[j].y);
                m1.z = fmaxf(m1.z, b[j].z); m1.w = fmaxf(m1.w, b[j].w);
            }
        }
    }

    *(float4*)&s_sum[w][4 * lane]       = s0;
    *(float4*)&s_sum[w][128 + 4 * lane] = s1;
    *(float4*)&s_max[w][4 * lane]       = m0;
    *(float4*)&s_max[w][128 + 4 * lane] = m1;
    __syncthreads();

    // fully parallel merge: each of 512 threads owns ONE output scalar.
    // warps 0-7 -> max[d], warps 8-15 -> mean[d]  (uniform branch per warp)
    {
        const bool is_max = (tid < 256);
        const int  d = tid & 255;

        float r;
        if (is_max) {
            r = s_max[0][d];
            #pragma unroll
            for (int q = 1; q < NW; ++q) r = fmaxf(r, s_max[q][d]);
            if (len < (float)L_) r = fmaxf(r, 0.0f);  // masked-out tokens add 0 to max
            out[(size_t)ne * (2 * D_) + d] = r;
        } else {
            r = s_sum[0][d];
            #pragma unroll
            for (int q = 1; q < NW; ++q) r += s_sum[q][d];
            r *= 1.0f / ((len > 0.0f) ? len : 1.0f);
            out[(size_t)ne * (2 * D_) + D_ + d] = r;
        }
    }
}

extern "C" void kernel_launch(void* const* d_in, const int* in_sizes, int n_in,
                              void* d_out, int out_size)
{
    const float* doc_state     = (const float*)d_in[0];
    const float* nodes_mapping = (const float*)d_in[1];
    const float* nodes_len     = (const float*)d_in[2];
    float* out = (float*)d_out;

    meanmax_kernel<<<N_ * E_, NW * 32>>>(doc_state, nodes_mapping, nodes_len, out);
}